// round 9
// baseline (speedup 1.0000x reference)
#include <cuda_runtime.h>
#include <cstdint>

// ---------------- problem constants ----------------
#define NCTA 148
#define NTHR 512
#define B    64
#define H    512
#define V    32000
#define S    64

#define KC    32          // k-chunk
#define PCH   36          // chunk row pitch (floats): 144B, 16B-aligned, conflict-free phases
#define FVT   256         // FC vocab rows per CTA (125 CTAs, exact)
#define NFC   125
#define GCTA  128         // gates CTAs (i-tile 4 each -> 512)
#define GT    4           // h-slice per gates CTA

// smem arena (floats) -- FC and gates overlay (phases are barrier-separated)
#define ACH   (B*PCH)          // 2304
#define FWCH  (FVT*PCH)        // 9216
#define GWCH  (12*PCH)         // 432
#define F_H   0                // 2*2304  = 4608
#define F_W   4608             // 2*9216 -> 23040
#define G_AE  0                // 2*2304
#define G_AH  4608             // 2*2304
#define G_WI  9216             // 2*432
#define G_WH  10080            // 2*432
#define G_SCR 10944            // 24*64 = 1536
#define G_TOK 12480            // 64 ints
#define SMEM_FLOATS 23040
#define SMEM_BYTES  (SMEM_FLOATS * 4)

// ---------------- persistent device state ----------------
__device__ float g_hbuf[2][B*H];
__device__ unsigned long long g_keybuf[2][B];
__device__ unsigned g_count;

// ---------------- helpers ----------------
union F2U { float2 f; unsigned long long u; };

static __device__ __forceinline__ float2 ffma2(float2 a, float2 b, float2 c) {
    F2U A, Bv, C, D;
    A.f = a; Bv.f = b; C.f = c;
    asm("fma.rn.f32x2 %0, %1, %2, %3;" : "=l"(D.u) : "l"(A.u), "l"(Bv.u), "l"(C.u));
    return D.f;
}

static __device__ __forceinline__ void cpasync16(float* dst, const float* src) {
    unsigned d = (unsigned)__cvta_generic_to_shared(dst);
    asm volatile("cp.async.cg.shared.global [%0], [%1], 16;" :: "r"(d), "l"(src));
}
static __device__ __forceinline__ void cp_commit() {
    asm volatile("cp.async.commit_group;");
}
template<int N> static __device__ __forceinline__ void cp_wait() {
    asm volatile("cp.async.wait_group %0;" :: "n"(N));
}

static __device__ __forceinline__ void gsync(unsigned target) {
    __syncthreads();
    if (threadIdx.x == 0) {
        __threadfence();
        atomicAdd(&g_count, 1u);
        while (*(volatile unsigned*)&g_count < target) { __nanosleep(32); }
        __threadfence();
    }
    __syncthreads();
}

// sortable key: larger pred -> larger key; ties -> smaller v wins (jnp.argmax first-hit)
static __device__ __forceinline__ unsigned long long makeKey(float p, int v) {
    unsigned u = __float_as_uint(p);
    u = (u & 0x80000000u) ? ~u : (u | 0x80000000u);
    return ((unsigned long long)u << 32) | (unsigned long long)(0xFFFFFFFFu - (unsigned)v);
}

// ---------------- fused gates + GRU combine ----------------
static __device__ void gates_combine(int cta, int tid,
                                     const float* __restrict__ Wih, const float* __restrict__ Whh,
                                     const float* __restrict__ bih, const float* __restrict__ bhh,
                                     const float* __restrict__ emb, const int* __restrict__ src,
                                     const float* __restrict__ hR, float* __restrict__ hW,
                                     const unsigned long long* __restrict__ keyR,
                                     int t, bool enc)
{
    extern __shared__ float sm[];
    float* ae  = sm + G_AE;
    float* ah  = sm + G_AH;
    float* wi  = sm + G_WI;
    float* wh  = sm + G_WH;
    float* scr = sm + G_SCR;
    int*  tok_s = (int*)(sm + G_TOK);

    if (cta >= GCTA) return;
    const int i0 = cta * GT;

    if (tid < B) {
        int tok;
        if (enc)          tok = src[tid*S + t];
        else if (t == 0)  tok = 0;  // SOS
        else {
            unsigned long long k = __ldcg(&keyR[tid]);
            tok = (int)(0xFFFFFFFFu - (unsigned)(k & 0xFFFFFFFFull));
        }
        tok_s[tid] = tok;
    }
    __syncthreads();

    auto issue = [&](int c, int p) {
        const int k0 = c * KC;
        {   // ae + ah: 64 rows x 8 float4 each
            int r = tid >> 3, q = tid & 7;
            cpasync16(ae + p*ACH + r*PCH + 4*q, emb + (size_t)tok_s[r]*H + k0 + 4*q);
            cpasync16(ah + p*ACH + r*PCH + 4*q, hR + r*H + k0 + 4*q);
        }
        if (tid < 96) {   // wi + wh: 12 rows x 8 float4 each; row r: j = (r/4)*512 + i0 + r%4
            int r = tid >> 3, q = tid & 7;
            int j = (r >> 2)*512 + i0 + (r & 3);
            cpasync16(wi + p*GWCH + r*PCH + 4*q, Wih + (size_t)j*H + k0 + 4*q);
            cpasync16(wh + p*GWCH + r*PCH + 4*q, Whh + (size_t)j*H + k0 + 4*q);
        }
        cp_commit();
    };

    const int lane = tid & 31, wy = tid >> 5;
    const int bh = wy & 1, jg = wy >> 1;        // jg 0..7 -> local rows 3jg..3jg+2
    const int b  = bh*32 + lane;
    const bool isGh = (jg >= GT);               // jg 0..3 -> gi (rows 0..11), 4..7 -> gh
    const int lr0 = (isGh ? (jg - GT) : jg) * 3;

    float2 acc[3];
    #pragma unroll
    for (int s = 0; s < 3; s++) acc[s] = make_float2(0.f, 0.f);

    issue(0, 0);
    for (int c = 0; c < H/KC; c++) {
        const int p = c & 1;
        if (c + 1 < H/KC) issue(c + 1, p ^ 1);
        if (c + 1 < H/KC) cp_wait<1>(); else cp_wait<0>();
        __syncthreads();
        const float* ap = (isGh ? ah : ae) + p*ACH + b*PCH;
        const float* wp = (isGh ? wh : wi) + p*GWCH + lr0*PCH;
        #pragma unroll
        for (int q = 0; q < KC/4; q++) {
            float4 a4 = *(const float4*)(ap + 4*q);
            #pragma unroll
            for (int s = 0; s < 3; s++) {
                float4 w4 = *(const float4*)(wp + s*PCH + 4*q);
                acc[s] = ffma2(make_float2(a4.x, a4.y), make_float2(w4.x, w4.y), acc[s]);
                acc[s] = ffma2(make_float2(a4.z, a4.w), make_float2(w4.z, w4.w), acc[s]);
            }
        }
        __syncthreads();
    }

    // partials (+bias) to scratch[rr][b], rr = (isGh?12:0) + lr, lr = m*4 + io
    #pragma unroll
    for (int s = 0; s < 3; s++) {
        int lr = lr0 + s;
        int j  = (lr >> 2)*512 + i0 + (lr & 3);
        float bv = isGh ? bhh[j] : bih[j];
        scr[((isGh ? 12 : 0) + lr)*B + b] = acc[s].x + acc[s].y + bv;
    }
    __syncthreads();

    if (tid < B*GT) {
        int b2 = tid & 63, io = tid >> 6;
        float gir = scr[(0 + io)*B + b2],  ghr = scr[(12 + io)*B + b2];
        float giz = scr[(4 + io)*B + b2],  ghz = scr[(16 + io)*B + b2];
        float gin = scr[(8 + io)*B + b2],  ghn = scr[(20 + io)*B + b2];
        float r = 1.f / (1.f + expf(-(gir + ghr)));
        float z = 1.f / (1.f + expf(-(giz + ghz)));
        float n = tanhf(gin + r*ghn);
        float hold = __ldcg(hR + b2*H + i0 + io);
        __stcg(hW + b2*H + i0 + io, (1.f - z)*n + z*hold);
    }
}

// ---------------- FC + argmax ----------------
static __device__ void fc_pass(int cta, int tid,
                               const float* __restrict__ fcW, const float* __restrict__ fcb,
                               const float* __restrict__ hR,
                               unsigned long long* __restrict__ keyW,
                               unsigned long long* __restrict__ keyReset,
                               float* __restrict__ out, int t, int T)
{
    extern __shared__ float sm[];
    float* h_s = sm + F_H;
    float* w_s = sm + F_W;
    if (cta >= NFC) return;
    const int v0 = cta * FVT;

    if (tid < B) __stcg(&keyReset[tid], 0ull);   // reset NEXT step's key buffer

    auto issue = [&](int c, int p) {
        const int k0 = c * KC;
        {   // h chunk: 64 rows x 8 float4
            int r = tid >> 3, q = tid & 7;
            cpasync16(h_s + p*ACH + r*PCH + 4*q, hR + r*H + k0 + 4*q);
        }
        #pragma unroll
        for (int k = 0; k < 4; k++) {            // w chunk: 256 rows x 8 float4
            int idx = tid + k*NTHR;
            int r = idx >> 3, q = idx & 7;
            cpasync16(w_s + p*FWCH + r*PCH + 4*q, fcW + (size_t)(v0 + r)*H + k0 + 4*q);
        }
        cp_commit();
    };

    const int tx = tid & 31, wy = tid >> 5;
    const int vg = wy >> 3, bg = wy & 7;         // v = v0+vg*128+tx+32i, b = bg*8+j
    float2 acc[4][8];
    #pragma unroll
    for (int i = 0; i < 4; i++)
        #pragma unroll
        for (int j = 0; j < 8; j++) acc[i][j] = make_float2(0.f, 0.f);

    issue(0, 0);
    for (int c = 0; c < H/KC; c++) {
        const int p = c & 1;
        if (c + 1 < H/KC) issue(c + 1, p ^ 1);
        if (c + 1 < H/KC) cp_wait<1>(); else cp_wait<0>();
        __syncthreads();
        const float* hb = h_s + p*ACH + (bg*8)*PCH;
        const float* wb = w_s + p*FWCH + (vg*128 + tx)*PCH;
        #pragma unroll
        for (int q = 0; q < KC/4; q++) {
            float4 h4[8];
            #pragma unroll
            for (int j = 0; j < 8; j++) h4[j] = *(const float4*)(hb + j*PCH + 4*q);
            #pragma unroll
            for (int i = 0; i < 4; i++) {
                float4 w4 = *(const float4*)(wb + i*32*PCH + 4*q);
                #pragma unroll
                for (int j = 0; j < 8; j++) {
                    acc[i][j] = ffma2(make_float2(h4[j].x, h4[j].y),
                                      make_float2(w4.x, w4.y), acc[i][j]);
                    acc[i][j] = ffma2(make_float2(h4[j].z, h4[j].w),
                                      make_float2(w4.z, w4.w), acc[i][j]);
                }
            }
        }
        __syncthreads();
    }

    unsigned long long bestKey[8];
    #pragma unroll
    for (int j = 0; j < 8; j++) bestKey[j] = 0ull;

    #pragma unroll
    for (int i = 0; i < 4; i++) {
        int v = v0 + vg*128 + tx + 32*i;
        float bv = fcb[v];
        #pragma unroll
        for (int j = 0; j < 8; j++) {
            float p = acc[i][j].x + acc[i][j].y + bv;
            int b = bg*8 + j;
            __stcs(out + ((size_t)b*T + t)*V + v, p);   // streaming store: keep fcW L2-resident
            unsigned long long key = makeKey(p, v);
            if (key > bestKey[j]) bestKey[j] = key;
        }
    }
    #pragma unroll
    for (int j = 0; j < 8; j++) {
        unsigned long long k = bestKey[j];
        #pragma unroll
        for (int off = 16; off > 0; off >>= 1) {
            unsigned long long o = __shfl_down_sync(0xFFFFFFFFu, k, off);
            if (o > k) k = o;
        }
        if (tx == 0) atomicMax(&keyW[bg*8 + j], k);
    }
}

// ---------------- kernels ----------------
__global__ void init_kernel()
{
    int g = blockIdx.x * blockDim.x + threadIdx.x;
    if (g < 2*B*H) ((float*)g_hbuf)[g] = 0.f;
    if (g < 2*B)   ((unsigned long long*)g_keybuf)[g] = 0ull;
    if (g == 0)    g_count = 0u;
}

__global__ void __launch_bounds__(NTHR, 1) seq2seq_kernel(
    const int* __restrict__ src, const float* __restrict__ emb,
    const float* __restrict__ eWih, const float* __restrict__ eWhh,
    const float* __restrict__ ebih, const float* __restrict__ ebhh,
    const float* __restrict__ dWih, const float* __restrict__ dWhh,
    const float* __restrict__ dbih, const float* __restrict__ dbhh,
    const float* __restrict__ fcW,  const float* __restrict__ fcb,
    float* __restrict__ out, int T)
{
    const int cta = blockIdx.x, tid = threadIdx.x;
    unsigned gen = 0;
    int hp = 0;

    for (int t = 0; t < S; t++) {
        gates_combine(cta, tid, eWih, eWhh, ebih, ebhh, emb, src,
                      g_hbuf[hp], g_hbuf[hp ^ 1], nullptr, t, true);
        hp ^= 1;
        gsync(++gen * NCTA);
    }
    for (int t = 0; t < T; t++) {
        const unsigned long long* keyR = g_keybuf[(t + 1) & 1];  // fc(t-1) wrote here
        gates_combine(cta, tid, dWih, dWhh, dbih, dbhh, emb, src,
                      g_hbuf[hp], g_hbuf[hp ^ 1], keyR, t, false);
        hp ^= 1;
        gsync(++gen * NCTA);
        fc_pass(cta, tid, fcW, fcb, g_hbuf[hp],
                g_keybuf[t & 1], g_keybuf[(t + 1) & 1], out, t, T);
        gsync(++gen * NCTA);
    }
}

extern "C" void kernel_launch(void* const* d_in, const int* in_sizes, int n_in,
                              void* d_out, int out_size)
{
    const int*   src  = (const int*)  d_in[0];
    const float* emb  = (const float*)d_in[1];
    const float* eWih = (const float*)d_in[2];
    const float* eWhh = (const float*)d_in[3];
    const float* ebih = (const float*)d_in[4];
    const float* ebhh = (const float*)d_in[5];
    const float* dWih = (const float*)d_in[6];
    const float* dWhh = (const float*)d_in[7];
    const float* dbih = (const float*)d_in[8];
    const float* dbhh = (const float*)d_in[9];
    const float* fcW  = (const float*)d_in[10];
    const float* fcb  = (const float*)d_in[11];
    float* out = (float*)d_out;
    const int T = out_size / (B * V);   // 80

    cudaFuncSetAttribute(seq2seq_kernel,
                         cudaFuncAttributeMaxDynamicSharedMemorySize, SMEM_BYTES);

    init_kernel<<<128, 512>>>();
    seq2seq_kernel<<<NCTA, NTHR, SMEM_BYTES>>>(
        src, emb, eWih, eWhh, ebih, ebhh,
        dWih, dWhh, dbih, dbhh, fcW, fcb, out, T);
}